// round 8
// baseline (speedup 1.0000x reference)
#include <cuda_runtime.h>
#include <cuda_bf16.h>
#include <cstdint>
#include <cfloat>
#include <cstddef>

#define NLAB 4096
#define FEAT 512
#define BB   16
#define LL   512
#define SLAB 9600            /* 32*300 per label */
#define KCONV 1216           /* 1200 padded to 19*64 */

typedef unsigned int u32;
typedef unsigned long long u64;

// ---------------- device scratch (static; no allocation) ----------------
__device__ __align__(16) __nv_bfloat16 g_lab_hi[NLAB*SLAB + 2048];
__device__ __align__(16) __nv_bfloat16 g_lab_lo[NLAB*SLAB + 2048];
__device__ __align__(16) __nv_bfloat16 g_wr_hi [FEAT*KCONV];
__device__ __align__(16) __nv_bfloat16 g_wr_lo [FEAT*KCONV];
__device__ __align__(16) __nv_bfloat16 g_x_hi  [BB*LL*FEAT];
__device__ __align__(16) __nv_bfloat16 g_x_lo  [BB*LL*FEAT];
__device__ __align__(16) __nv_bfloat16 g_xt_hi [BB*FEAT*LL];
__device__ __align__(16) __nv_bfloat16 g_xt_lo [BB*FEAT*LL];
__device__ __align__(16) __nv_bfloat16 g_lw_hi [FEAT*FEAT];
__device__ __align__(16) __nv_bfloat16 g_lw_lo [FEAT*FEAT];
__device__ __align__(16) __nv_bfloat16 g_lr0_hi[NLAB*FEAT];
__device__ __align__(16) __nv_bfloat16 g_lr0_lo[NLAB*FEAT];
__device__ __align__(16) __nv_bfloat16 g_lr_hi [NLAB*FEAT];
__device__ __align__(16) __nv_bfloat16 g_lr_lo [NLAB*FEAT];
__device__ __align__(16) float         g_S     [(size_t)BB*NLAB*LL];
__device__ __align__(16) __nv_bfloat16 g_P_hi  [(size_t)BB*NLAB*LL];
__device__ __align__(16) __nv_bfloat16 g_P_lo  [(size_t)BB*NLAB*LL];

// ---------------- helpers ----------------
__device__ __forceinline__ u32 smem_u32(const void* p) {
    u32 a;
    asm("{ .reg .u64 t; cvta.to.shared.u64 t, %1; cvt.u32.u64 %0, t; }" : "=r"(a) : "l"(p));
    return a;
}
__device__ __forceinline__ void cp16(u32 dst, const void* src) {
    asm volatile("cp.async.cg.shared.global [%0], [%1], 16;" :: "r"(dst), "l"(src));
}
__device__ __forceinline__ void cp8(u32 dst, const void* src) {
    asm volatile("cp.async.ca.shared.global [%0], [%1], 8;" :: "r"(dst), "l"(src));
}
#define CP_COMMIT() asm volatile("cp.async.commit_group;" ::: "memory")
#define CP_WAIT(n)  asm volatile("cp.async.wait_group %0;" :: "n"(n) : "memory")

#define LDSM4(r, a)                                                                     \
    asm volatile("ldmatrix.sync.aligned.m8n8.x4.shared.b16 {%0,%1,%2,%3}, [%4];"        \
        : "=r"((r)[0]), "=r"((r)[1]), "=r"((r)[2]), "=r"((r)[3]) : "r"(a))

__device__ __forceinline__ void mma16816(float* d, const u32* a, const u32* b) {
    asm volatile(
        "mma.sync.aligned.m16n8k16.row.col.f32.bf16.bf16.f32 "
        "{%0,%1,%2,%3},{%4,%5,%6,%7},{%8,%9},{%0,%1,%2,%3};"
        : "+f"(d[0]), "+f"(d[1]), "+f"(d[2]), "+f"(d[3])
        : "r"(a[0]), "r"(a[1]), "r"(a[2]), "r"(a[3]), "r"(b[0]), "r"(b[1]));
}
__device__ __forceinline__ void split2(float v, __nv_bfloat16& h, __nv_bfloat16& l) {
    h = __float2bfloat16(v);
    l = __float2bfloat16(v - __bfloat162float(h));
}
__device__ __forceinline__ u32 packsplit(float a, float b, u32& lo) {
    __nv_bfloat16 ha, la, hb, lb;
    split2(a, ha, la); split2(b, hb, lb);
    __nv_bfloat162 H; H.x = ha; H.y = hb;
    __nv_bfloat162 L; L.x = la; L.y = lb;
    lo = *(u32*)&L;
    return *(u32*)&H;
}

// smem geometry: 4 tiles (Ahi, Alo, Bhi, Blo) of 128 rows x 64 bf16, rows padded to 144B
#define TROW   144
#define TILE_B (128 * TROW)          /* 18432 */
#define STAGE  (4 * TILE_B)          /* 73728 */
#define NSTAGE 3
#define SMEM_TOTAL (NSTAGE * STAGE)  /* 221184 */

// ================= split-bf16 HMMA GEMM (mma.sync m16n8k16) =================
// C[m,c] = sum_k A[m,k]*B[c,k], 3-product split for ~fp32 accuracy.
// MODE 0: conv  C[f,(n,t)]  A=wr, B=lab windows; epi: maxpool(t<29)+bias+relu -> lr0 hi/lo
// MODE 1: linear C[n,f]     A=lr0, B=lin_w;      epi: +bias -> lr hi/lo
// MODE 2: logits C[n,l]     A=lr, B=x[b];        epi: fp32 -> S
// MODE 3: out    C[n,f]     A=P[b], B=xt[b];     epi: fp32 -> d_out
template<int MODE>
__global__ void __launch_bounds__(256, 1) tgemm(
    const __nv_bfloat16* __restrict__ Ahi, const __nv_bfloat16* __restrict__ Alo,
    const __nv_bfloat16* __restrict__ Bhi, const __nv_bfloat16* __restrict__ Blo,
    const float* __restrict__ bias, float* __restrict__ Cf,
    __nv_bfloat16* __restrict__ Chi, __nv_bfloat16* __restrict__ Clo,
    size_t zA, size_t zB, size_t zC)
{
    extern __shared__ char smem[];
    const int tid = threadIdx.x, w = tid >> 5, lam = tid & 31;
    const int KA = (MODE == 0) ? KCONV : 512;
    const int NC = (MODE == 0) ? 19 : 8;
    const int m0 = (MODE == 0 ? blockIdx.x : blockIdx.y) * 128;   // A-side rows
    const int c0 = (MODE == 0 ? blockIdx.y : blockIdx.x) * 128;   // B-side cols
    const int z  = blockIdx.z;
    Ahi += (size_t)z * zA;  Alo += (size_t)z * zA;
    Bhi += (size_t)z * zB;  Blo += (size_t)z * zB;

    // ---- global->smem coords: 2 threads per row, halves of 64B each ----
    const int lrow = tid >> 1, lhalf = tid & 1;
    const size_t aBase = (size_t)(m0 + lrow) * KA + lhalf * 32;
    size_t bBase;
    if (MODE == 0) {
        const int col = c0 + lrow;
        bBase = (size_t)(col >> 5) * SLAB + (size_t)(col & 31) * 300 + lhalf * 32;
    } else {
        bBase = (size_t)(c0 + lrow) * 512 + lhalf * 32;
    }
    const u32 sb   = smem_u32(smem);
    const u32 dstA = sb + lrow * TROW + lhalf * 64;
    const u32 dstB = sb + 2 * TILE_B + lrow * TROW + lhalf * 64;

#define LOAD_STAGE(c, s) do {                                                        \
    const u32 so = (u32)(s) * STAGE;                                                 \
    const size_t ko = (size_t)(c) * 64;                                              \
    _Pragma("unroll") for (int q = 0; q < 4; ++q) {                                  \
        cp16(dstA + so + q*16,          Ahi + aBase + ko + q*8);                     \
        cp16(dstA + so + TILE_B + q*16, Alo + aBase + ko + q*8);                     \
    }                                                                                \
    if (MODE == 0) {                                                                 \
        _Pragma("unroll") for (int q = 0; q < 8; ++q) {                              \
            cp8(dstB + so + q*8,          Bhi + bBase + ko + q*4);                   \
            cp8(dstB + so + TILE_B + q*8, Blo + bBase + ko + q*4);                   \
        }                                                                            \
    } else {                                                                         \
        _Pragma("unroll") for (int q = 0; q < 4; ++q) {                              \
            cp16(dstB + so + q*16,          Bhi + bBase + ko + q*8);                 \
            cp16(dstB + so + TILE_B + q*16, Blo + bBase + ko + q*8);                 \
        }                                                                            \
    }                                                                                \
    CP_COMMIT();                                                                     \
} while (0)

    // ---- warp/lane fragment coords ----
    const int wm = (w >> 2) * 64, wn = (w & 3) * 32;
    const int aRow  = (lam & 7) + ((lam >> 3) & 1) * 8;
    const u32 aKoff = (lam >> 4) * 16;
    const int bRow  = (lam & 7) + (lam >> 4) * 8;
    const u32 bKoff = ((lam >> 3) & 1) * 16;

    float acc[4][4][4];
#pragma unroll
    for (int mi = 0; mi < 4; ++mi)
#pragma unroll
        for (int ni = 0; ni < 4; ++ni)
#pragma unroll
            for (int q = 0; q < 4; ++q) acc[mi][ni][q] = 0.f;

    LOAD_STAGE(0, 0);
    LOAD_STAGE(1, 1);

    for (int c = 0; c < NC; ++c) {
        const int s = c % NSTAGE;
        if (c + 2 < NC) { LOAD_STAGE(c + 2, (c + 2) % NSTAGE); CP_WAIT(2); }
        else if (c + 1 < NC) { CP_WAIT(1); }
        else { CP_WAIT(0); }
        __syncthreads();

        const u32 stA = sb + s * STAGE;
        const u32 stB = stA + 2 * TILE_B;
#pragma unroll
        for (int kk = 0; kk < 4; ++kk) {
            u32 ah[4][4], al[4][4], bh[4][2], bl[4][2];
#pragma unroll
            for (int mi = 0; mi < 4; ++mi) {
                const u32 a = stA + (wm + mi*16 + aRow) * TROW + kk*32 + aKoff;
                LDSM4(ah[mi], a);
                LDSM4(al[mi], a + TILE_B);
            }
#pragma unroll
            for (int nt = 0; nt < 2; ++nt) {
                const u32 a = stB + (wn + nt*16 + bRow) * TROW + kk*32 + bKoff;
                u32 t[4];
                LDSM4(t, a);
                bh[2*nt][0] = t[0]; bh[2*nt][1] = t[1];
                bh[2*nt+1][0] = t[2]; bh[2*nt+1][1] = t[3];
                LDSM4(t, a + TILE_B);
                bl[2*nt][0] = t[0]; bl[2*nt][1] = t[1];
                bl[2*nt+1][0] = t[2]; bl[2*nt+1][1] = t[3];
            }
#pragma unroll
            for (int mi = 0; mi < 4; ++mi)
#pragma unroll
                for (int ni = 0; ni < 4; ++ni) {
                    mma16816(acc[mi][ni], ah[mi], bh[ni]);
                    mma16816(acc[mi][ni], ah[mi], bl[ni]);
                    mma16816(acc[mi][ni], al[mi], bh[ni]);
                }
        }
        __syncthreads();
    }

    // ---- epilogue ----
    const int g = lam >> 2, i2 = (lam & 3) * 2;
    if (MODE == 0) {
        const int label = blockIdx.y * 4 + (w & 3);
#pragma unroll
        for (int mi = 0; mi < 4; ++mi) {
            float x0 = -FLT_MAX, x1 = -FLT_MAX;
#pragma unroll
            for (int ni = 0; ni < 4; ++ni)
#pragma unroll
                for (int j = 0; j < 2; ++j) {
                    const int t = ni * 8 + i2 + j;
                    if (t < 29) {
                        x0 = fmaxf(x0, acc[mi][ni][j]);
                        x1 = fmaxf(x1, acc[mi][ni][2 + j]);
                    }
                }
            x0 = fmaxf(x0, __shfl_xor_sync(0xffffffffu, x0, 1));
            x0 = fmaxf(x0, __shfl_xor_sync(0xffffffffu, x0, 2));
            x1 = fmaxf(x1, __shfl_xor_sync(0xffffffffu, x1, 1));
            x1 = fmaxf(x1, __shfl_xor_sync(0xffffffffu, x1, 2));
            if ((lam & 3) == 0) {
                const int f0 = m0 + wm + mi * 16 + g;
                float v = fmaxf(x0 + bias[f0], 0.f);
                __nv_bfloat16 h, l; split2(v, h, l);
                Chi[(size_t)label * FEAT + f0] = h;
                Clo[(size_t)label * FEAT + f0] = l;
                const int f1 = f0 + 8;
                v = fmaxf(x1 + bias[f1], 0.f);
                split2(v, h, l);
                Chi[(size_t)label * FEAT + f1] = h;
                Clo[(size_t)label * FEAT + f1] = l;
            }
        }
    } else if (MODE == 1) {
#pragma unroll
        for (int mi = 0; mi < 4; ++mi)
#pragma unroll
            for (int ni = 0; ni < 4; ++ni) {
                const int row = m0 + wm + mi * 16 + g;
                const int col = c0 + wn + ni * 8 + i2;
                __nv_bfloat16 h, l;
                float v = acc[mi][ni][0] + bias[col];
                split2(v, h, l); Chi[(size_t)row*512 + col] = h;     Clo[(size_t)row*512 + col] = l;
                v = acc[mi][ni][1] + bias[col + 1];
                split2(v, h, l); Chi[(size_t)row*512 + col + 1] = h; Clo[(size_t)row*512 + col + 1] = l;
                v = acc[mi][ni][2] + bias[col];
                split2(v, h, l); Chi[(size_t)(row+8)*512 + col] = h; Clo[(size_t)(row+8)*512 + col] = l;
                v = acc[mi][ni][3] + bias[col + 1];
                split2(v, h, l); Chi[(size_t)(row+8)*512 + col + 1] = h; Clo[(size_t)(row+8)*512 + col + 1] = l;
            }
    } else {
        float* base = Cf + (size_t)z * zC;
#pragma unroll
        for (int mi = 0; mi < 4; ++mi)
#pragma unroll
            for (int ni = 0; ni < 4; ++ni) {
                const int row = m0 + wm + mi * 16 + g;
                const int col = c0 + wn + ni * 8 + i2;
                *(float2*)(base + (size_t)row * 512 + col) =
                    make_float2(acc[mi][ni][0], acc[mi][ni][1]);
                *(float2*)(base + (size_t)(row + 8) * 512 + col) =
                    make_float2(acc[mi][ni][2], acc[mi][ni][3]);
            }
    }
#undef LOAD_STAGE
}

// ---------------- conversion kernels (vectorized: 8 floats/thread) ----------------
__global__ void cvt8(const float4* __restrict__ in, uint4* __restrict__ H,
                     uint4* __restrict__ L) {
    const int i = blockIdx.x * 256 + threadIdx.x;
    const float4 a = in[2*i], b = in[2*i+1];
    u32 l0, l1, l2, l3;
    uint4 h;
    h.x = packsplit(a.x, a.y, l0);
    h.y = packsplit(a.z, a.w, l1);
    h.z = packsplit(b.x, b.y, l2);
    h.w = packsplit(b.z, b.w, l3);
    H[i] = h;
    L[i] = make_uint4(l0, l1, l2, l3);
}
__global__ void pad_lab() {
    int i = blockIdx.x * 256 + threadIdx.x;            // 2048
    g_lab_hi[NLAB*SLAB + i] = __float2bfloat16(0.f);
    g_lab_lo[NLAB*SLAB + i] = __float2bfloat16(0.f);
}
__global__ void cvt_wr(const float* __restrict__ cw) {
    int i = blockIdx.x * 256 + threadIdx.x;            // 512*1216 exact
    int f = i / KCONV, j = i % KCONV;
    float v = (j < 1200) ? cw[f * 1200 + (j % 300) * 4 + (j / 300)] : 0.f;
    __nv_bfloat16 h, l; split2(v, h, l);
    g_wr_hi[i] = h; g_wr_lo[i] = l;
}
// transpose x[b,l,f] -> xt[b,f,l], split hi/lo; 64l x 32f tiles
__global__ void cvt_xt_k(const float* __restrict__ x) {
    __shared__ float tile[64][33];
    const int b = blockIdx.z, lt = blockIdx.x * 64, ft = blockIdx.y * 32;
    const int tx = threadIdx.x & 31, ty = threadIdx.x >> 5;
    const size_t xb = (size_t)b << 18;
#pragma unroll
    for (int r = 0; r < 64; r += 8)
        tile[r + ty][tx] = x[xb + (size_t)(lt + r + ty) * 512 + ft + tx];
    __syncthreads();
#pragma unroll
    for (int r = 0; r < 32; r += 8) {
        const int fc = r + ty;
        const float v0 = tile[2*tx][fc], v1 = tile[2*tx+1][fc];
        __nv_bfloat16 h0, l0, h1, l1;
        split2(v0, h0, l0); split2(v1, h1, l1);
        __nv_bfloat162 H; H.x = h0; H.y = h1;
        __nv_bfloat162 L; L.x = l0; L.y = l1;
        const size_t o = xb + (size_t)(ft + fc) * 512 + lt + 2*tx;
        *(__nv_bfloat162*)&g_xt_hi[o] = H;
        *(__nv_bfloat162*)&g_xt_lo[o] = L;
    }
}

// ---------------- softmax over L=512, outputs split bf16 ----------------
__global__ void softmax_kernel(const float* __restrict__ S,
                               __nv_bfloat16* __restrict__ Ph,
                               __nv_bfloat16* __restrict__ Pl) {
    const size_t row = blockIdx.x;
    const float* p = S + row * 512;
    const int tid = threadIdx.x;   // 128
    float v0 = p[tid], v1 = p[tid + 128], v2 = p[tid + 256], v3 = p[tid + 384];
    float mx = fmaxf(fmaxf(v0, v1), fmaxf(v2, v3));
#pragma unroll
    for (int o = 16; o > 0; o >>= 1) mx = fmaxf(mx, __shfl_xor_sync(0xffffffffu, mx, o));
    __shared__ float sm[4], ss[4];
    if ((tid & 31) == 0) sm[tid >> 5] = mx;
    __syncthreads();
    mx = fmaxf(fmaxf(sm[0], sm[1]), fmaxf(sm[2], sm[3]));
    v0 = __expf(v0 - mx); v1 = __expf(v1 - mx); v2 = __expf(v2 - mx); v3 = __expf(v3 - mx);
    float s = v0 + v1 + v2 + v3;
#pragma unroll
    for (int o = 16; o > 0; o >>= 1) s += __shfl_xor_sync(0xffffffffu, s, o);
    if ((tid & 31) == 0) ss[tid >> 5] = s;
    __syncthreads();
    s = ss[0] + ss[1] + ss[2] + ss[3];
    const float inv = 1.0f / s;
    const size_t b = row * 512;
    __nv_bfloat16 h, l;
    split2(v0 * inv, h, l); Ph[b + tid]       = h; Pl[b + tid]       = l;
    split2(v1 * inv, h, l); Ph[b + tid + 128] = h; Pl[b + tid + 128] = l;
    split2(v2 * inv, h, l); Ph[b + tid + 256] = h; Pl[b + tid + 256] = l;
    split2(v3 * inv, h, l); Ph[b + tid + 384] = h; Pl[b + tid + 384] = l;
}

// ---------------- launch ----------------
extern "C" void kernel_launch(void* const* d_in, const int* in_sizes, int n_in,
                              void* d_out, int out_size) {
    const float *x = nullptr, *lab = nullptr, *cw = nullptr,
                *cb = nullptr, *lw = nullptr, *lb = nullptr;
    for (int i = 0; i < n_in; ++i) {
        switch (in_sizes[i]) {
            case 4194304:  x   = (const float*)d_in[i]; break;
            case 39321600: lab = (const float*)d_in[i]; break;
            case 614400:   cw  = (const float*)d_in[i]; break;
            case 262144:   lw  = (const float*)d_in[i]; break;
            case 512:      if (!cb) cb = (const float*)d_in[i];
                           else     lb = (const float*)d_in[i];
                           break;
            default: break;   // label_length unused
        }
    }

    __nv_bfloat16 *labh, *labl, *wrh, *wrl, *xh, *xl, *xth, *xtl, *lwh, *lwl,
                  *lr0h, *lr0l, *lrh, *lrl, *Ph, *Pl;
    float *pS;
    cudaGetSymbolAddress((void**)&labh, g_lab_hi); cudaGetSymbolAddress((void**)&labl, g_lab_lo);
    cudaGetSymbolAddress((void**)&wrh,  g_wr_hi);  cudaGetSymbolAddress((void**)&wrl,  g_wr_lo);
    cudaGetSymbolAddress((void**)&xh,   g_x_hi);   cudaGetSymbolAddress((void**)&xl,   g_x_lo);
    cudaGetSymbolAddress((void**)&xth,  g_xt_hi);  cudaGetSymbolAddress((void**)&xtl,  g_xt_lo);
    cudaGetSymbolAddress((void**)&lwh,  g_lw_hi);  cudaGetSymbolAddress((void**)&lwl,  g_lw_lo);
    cudaGetSymbolAddress((void**)&lr0h, g_lr0_hi); cudaGetSymbolAddress((void**)&lr0l, g_lr0_lo);
    cudaGetSymbolAddress((void**)&lrh,  g_lr_hi);  cudaGetSymbolAddress((void**)&lrl,  g_lr_lo);
    cudaGetSymbolAddress((void**)&Ph,   g_P_hi);   cudaGetSymbolAddress((void**)&Pl,   g_P_lo);
    cudaGetSymbolAddress((void**)&pS,   g_S);

    cudaFuncSetAttribute(tgemm<0>, cudaFuncAttributeMaxDynamicSharedMemorySize, SMEM_TOTAL);
    cudaFuncSetAttribute(tgemm<1>, cudaFuncAttributeMaxDynamicSharedMemorySize, SMEM_TOTAL);
    cudaFuncSetAttribute(tgemm<2>, cudaFuncAttributeMaxDynamicSharedMemorySize, SMEM_TOTAL);
    cudaFuncSetAttribute(tgemm<3>, cudaFuncAttributeMaxDynamicSharedMemorySize, SMEM_TOTAL);

    pad_lab<<<8, 256>>>();
    cvt8<<<19200, 256>>>((const float4*)lab, (uint4*)labh, (uint4*)labl);  // 39321600
    cvt_wr<<<2432, 256>>>(cw);
    cvt8<<<2048,  256>>>((const float4*)x,  (uint4*)xh,  (uint4*)xl);      // 4194304
    cvt8<<<128,   256>>>((const float4*)lw, (uint4*)lwh, (uint4*)lwl);     // 262144
    cvt_xt_k<<<dim3(8, 16, 16), 256>>>(x);

    // conv: C[f, (n,t)], maxpool+bias+relu -> lr0 hi/lo
    tgemm<0><<<dim3(4, 1024, 1), 256, SMEM_TOTAL>>>(wrh, wrl, labh, labl, cb,
                                                    nullptr, lr0h, lr0l, 0, 0, 0);
    // linear: lr = lr0 @ lin_w^T + lin_b (both operands k(f_in)-major)
    tgemm<1><<<dim3(4, 32, 1),   256, SMEM_TOTAL>>>(lr0h, lr0l, lwh, lwl, lb,
                                                    nullptr, lrh, lrl, 0, 0, 0);
    // logits: S[b,n,l] = lr[n,:] . x[b,l,:]
    tgemm<2><<<dim3(4, 32, 16),  256, SMEM_TOTAL>>>(lrh, lrl, xh, xl, nullptr,
                                                    pS, nullptr, nullptr,
                                                    0, (size_t)LL * FEAT, (size_t)NLAB * LL);
    softmax_kernel<<<65536, 128>>>(pS, Ph, Pl);
    // out: O[b,n,f] = P[b,n,:] . xT[b,f,:]
    tgemm<3><<<dim3(4, 32, 16),  256, SMEM_TOTAL>>>(Ph, Pl, xth, xtl, nullptr,
                                                    (float*)d_out, nullptr, nullptr,
                                                    (size_t)NLAB * LL, (size_t)FEAT * LL,
                                                    (size_t)NLAB * FEAT);
}